// round 13
// baseline (speedup 1.0000x reference)
#include <cuda_runtime.h>
#include <cuda_fp16.h>
#include <cstdint>

// ============================================================================
// Portable tensor-core path: mma.sync.m16n8k16 (f16 in, f32 accum).
// The harness compiles for plain sm_100 (no 'a' suffix) -> no tcgen05.
// Iter kernel is the proven floor config (163.9us, rel_err 2.05e-4):
//   11.53M HMMAs x rt16 / 592 SMSP @ ~1.9GHz = 163.7us.
// This round: single merged prep kernel (one launch fewer, no partials pass).
// ============================================================================

static constexpr int E = 64;
static constexpr int IN_DIM = 512;
static constexpr int NCLS = 10;

#define SWZ(o) ((o) ^ (((o) >> 3) & 0x70))

__device__ __forceinline__ uint32_t packh2(float a, float b) {
    __half2 h = __floats2half2_rn(a, b);
    return *reinterpret_cast<uint32_t*>(&h);
}

__device__ __forceinline__ void mma16816(float d[4], const uint32_t a[4], uint2 b) {
    asm volatile(
        "mma.sync.aligned.m16n8k16.row.col.f32.f16.f16.f32 "
        "{%0,%1,%2,%3}, {%4,%5,%6,%7}, {%8,%9}, {%0,%1,%2,%3};\n"
        : "+f"(d[0]), "+f"(d[1]), "+f"(d[2]), "+f"(d[3])
        : "r"(a[0]), "r"(a[1]), "r"(a[2]), "r"(a[3]), "r"(b.x), "r"(b.y));
}

// ============================================================================
// Device scratch (no dynamic allocation allowed)
// ============================================================================
__device__ __align__(16) uint2 g_W1zF[8 * 4 * 32];      // B-frags of W1[:, 64:128]
__device__ __align__(16) uint2 g_W2F[8 * 4 * 32];       // B-frags of 0.1*W2
__device__ __align__(16) uint2 g_WcF[32 * 8 * 32];      // B-frags of Wc (K=512)
__device__ __align__(16) float g_bias1[E];              // b1 + W1[:, :64] @ b_feat
__device__ __align__(16) float g_w1t[E];                // W1[:, 128]

// ============================================================================
// Single prep kernel: all fragments + folded constants, no partials pass.
// WcF section computes Wc = W1[:, :64] @ W_feat dots directly (K=64).
// B frag for m16n8k16.col: lane L (g=L>>2, t=L&3), n-tile j, k-chunk q:
//   b0 = {W[8j+g][16q+2t],   W[8j+g][16q+2t+1]}
//   b1 = {W[8j+g][16q+2t+8], W[8j+g][16q+2t+9]}
// ============================================================================
__global__ void prep_kernel(const float* __restrict__ W_feat,
                            const float* __restrict__ b_feat,
                            const float* __restrict__ W1,
                            const float* __restrict__ b1,
                            const float* __restrict__ W2) {
    int idx = blockIdx.x * 256 + threadIdx.x;
    if (idx < 8192) {                                   // WcF: direct K=64 dots
        int L = idx & 31, j = (idx >> 5) & 7, q = idx >> 8;
        int n = 8 * j + (L >> 2), k0 = 16 * q + 2 * (L & 3);
        const float* w1row = W1 + n * 129;
        float acc[4] = {0.f, 0.f, 0.f, 0.f};
        #pragma unroll 8
        for (int e = 0; e < E; e++) {
            float w = w1row[e];
            const float* wf = W_feat + e * IN_DIM + k0;
            acc[0] = fmaf(w, wf[0], acc[0]);
            acc[1] = fmaf(w, wf[1], acc[1]);
            acc[2] = fmaf(w, wf[8], acc[2]);
            acc[3] = fmaf(w, wf[9], acc[3]);
        }
        g_WcF[idx] = make_uint2(packh2(acc[0], acc[1]), packh2(acc[2], acc[3]));
    } else if (idx < 9216) {                            // W1zF
        int f = idx - 8192;
        int L = f & 31, q = (f >> 5) & 3, j = f >> 7;
        int n = 8 * j + (L >> 2), k0 = 16 * q + 2 * (L & 3);
        const float* w = W1 + n * 129 + 64;
        g_W1zF[f] = make_uint2(packh2(w[k0], w[k0 + 1]),
                               packh2(w[k0 + 8], w[k0 + 9]));
    } else if (idx < 10240) {                           // W2F (pre-scaled by 0.1)
        int f = idx - 9216;
        int L = f & 31, q = (f >> 5) & 3, j = f >> 7;
        int n = 8 * j + (L >> 2), k0 = 16 * q + 2 * (L & 3);
        const float* w = W2 + n * E;
        g_W2F[f] = make_uint2(packh2(0.1f * w[k0], 0.1f * w[k0 + 1]),
                              packh2(0.1f * w[k0 + 8], 0.1f * w[k0 + 9]));
    } else if (idx < 10240 + E) {                       // bias1, w1t
        int n = idx - 10240;
        float acc = b1[n];
        for (int e = 0; e < E; e++) acc += W1[n * 129 + e] * b_feat[e];
        g_bias1[n] = acc;
        g_w1t[n] = W1[n * 129 + 128];
    }
}

// ============================================================================
// Main kernel: 128 threads = 4 warps, 32 rows/warp. Register-resident
// recurrence, no in-loop synchronization of any kind. (Proven 163.9us.)
// ============================================================================
__global__ __launch_bounds__(128, 2)
void iter_kernel(const float* __restrict__ x,
                 const float* __restrict__ z0,
                 const float* __restrict__ b2,
                 const float* __restrict__ class_emb,
                 const int* __restrict__ Tptr,
                 float* __restrict__ out,
                 int Bn) {
    __shared__ __align__(16) uint2 sW1z[1024];          // 8 KB
    __shared__ __align__(16) uint2 sW2[1024];           // 8 KB
    __shared__ float sBias1[E], sW1t[E], sB2s[E];
    __shared__ float sCE[NCLS * E];
    __shared__ __align__(128) char sX[128 * 128];       // 16 KB fp16, swizzled

    const int tid  = threadIdx.x;
    const int lane = tid & 31;
    const int g    = lane >> 2;
    const int t4   = lane & 3;
    const int warp = tid >> 5;
    const int ctabase = blockIdx.x * 128;
    const int rowbase = ctabase + warp * 32;

    // ---- cooperative weight/constant loads ----
    for (int i = tid; i < 1024; i += 128) { sW1z[i] = g_W1zF[i]; sW2[i] = g_W2F[i]; }
    if (tid < E) {
        sBias1[tid] = g_bias1[tid];
        sW1t[tid]   = g_w1t[tid];
        sB2s[tid]   = 0.1f * b2[tid];
    }
    for (int i = tid; i < NCLS * E; i += 128) sCE[i] = class_emb[i];

    // ======================= u = x @ Wc^T  (K = 512) =======================
    float u[2][8][4];
    #pragma unroll
    for (int i = 0; i < 2; i++)
        #pragma unroll
        for (int j = 0; j < 8; j++)
            #pragma unroll
            for (int c = 0; c < 4; c++) u[i][j][c] = 0.f;

    for (int ch = 0; ch < 8; ch++) {
        __syncthreads();   // protect sX reuse (also covers initial weight loads)
        // stage 128 rows x 64 cols fp32 -> fp16, swizzled
        for (int s = tid; s < 1024; s += 128) {
            int r = s >> 3, cq = s & 7;
            int rr = ctabase + r; if (rr >= Bn) rr = Bn - 1;
            const float4* p = (const float4*)(x + (size_t)rr * IN_DIM + ch * 64 + cq * 8);
            float4 v0 = p[0], v1 = p[1];
            uint4 pk;
            pk.x = packh2(v0.x, v0.y); pk.y = packh2(v0.z, v0.w);
            pk.z = packh2(v1.x, v1.y); pk.w = packh2(v1.z, v1.w);
            *(uint4*)(sX + SWZ(r * 128 + cq * 16)) = pk;
        }
        __syncthreads();
        #pragma unroll
        for (int q = 0; q < 4; q++) {
            uint32_t a[2][4];
            #pragma unroll
            for (int i = 0; i < 2; i++) {
                int rb0 = (warp * 32 + i * 16 + g) * 128;
                int rb1 = rb0 + 8 * 128;
                int cb  = q * 32 + t4 * 4;
                a[i][0] = *(const uint32_t*)(sX + SWZ(rb0 + cb));
                a[i][1] = *(const uint32_t*)(sX + SWZ(rb1 + cb));
                a[i][2] = *(const uint32_t*)(sX + SWZ(rb0 + cb + 16));
                a[i][3] = *(const uint32_t*)(sX + SWZ(rb1 + cb + 16));
            }
            #pragma unroll
            for (int j = 0; j < 8; j++) {
                uint2 b = g_WcF[((ch * 4 + q) * 8 + j) * 32 + lane];
                mma16816(u[0][j], a[0], b);
                mma16816(u[1][j], a[1], b);
            }
        }
    }
    __syncthreads();

    // ---- fold bias1 into u, compress to half2 (frees 32 regs) ----
    uint32_t uh[2][8][2];
    #pragma unroll
    for (int j = 0; j < 8; j++) {
        float b0 = sBias1[8 * j + 2 * t4], b1v = sBias1[8 * j + 2 * t4 + 1];
        #pragma unroll
        for (int i = 0; i < 2; i++) {
            uh[i][j][0] = packh2(u[i][j][0] + b0, u[i][j][1] + b1v);
            uh[i][j][1] = packh2(u[i][j][2] + b0, u[i][j][3] + b1v);
        }
    }

    float w1tv[8][2], b2v[8][2];
    #pragma unroll
    for (int j = 0; j < 8; j++) {
        w1tv[j][0] = sW1t[8 * j + 2 * t4];  w1tv[j][1] = sW1t[8 * j + 2 * t4 + 1];
        b2v[j][0]  = sB2s[8 * j + 2 * t4];  b2v[j][1]  = sB2s[8 * j + 2 * t4 + 1];
    }

    // ---- z0 -> registers (D-fragment layout, fp32 master) ----
    float z[2][8][4];
    #pragma unroll
    for (int i = 0; i < 2; i++) {
        int r0 = rowbase + i * 16 + g; if (r0 >= Bn) r0 = Bn - 1;
        int r1 = r0 + 8;               if (r1 >= Bn) r1 = Bn - 1;
        #pragma unroll
        for (int j = 0; j < 8; j++) {
            float2 v0 = *(const float2*)(z0 + (size_t)r0 * E + 8 * j + 2 * t4);
            float2 v1 = *(const float2*)(z0 + (size_t)r1 * E + 8 * j + 2 * t4);
            z[i][j][0] = v0.x; z[i][j][1] = v0.y;
            z[i][j][2] = v1.x; z[i][j][3] = v1.y;
        }
    }

    // ---- T ----
    int T = Tptr ? Tptr[0] : 40;
    if (T <= 0 || T > 1000000) {
        float tf = __int_as_float(T);
        T = (tf > 0.5f && tf < 1.0e6f) ? (int)tf : 40;
    }
    const float invT = 1.0f / (float)T;

    // ======================= 40-step recurrence (registers only) ============
    for (int step = 0; step < T; step++) {
        const float tv = (float)step * invT;

        // ---- GEMM1: d = u + t*w1t + z @ W1z^T ----
        float d[2][8][4];
        #pragma unroll
        for (int i = 0; i < 2; i++)
            #pragma unroll
            for (int j = 0; j < 8; j++) {
                float2 lo = __half22float2(*reinterpret_cast<__half2*>(&uh[i][j][0]));
                float2 hi = __half22float2(*reinterpret_cast<__half2*>(&uh[i][j][1]));
                d[i][j][0] = fmaf(tv, w1tv[j][0], lo.x);
                d[i][j][1] = fmaf(tv, w1tv[j][1], lo.y);
                d[i][j][2] = fmaf(tv, w1tv[j][0], hi.x);
                d[i][j][3] = fmaf(tv, w1tv[j][1], hi.y);
            }
        #pragma unroll
        for (int q = 0; q < 4; q++) {
            uint32_t a[2][4];
            #pragma unroll
            for (int i = 0; i < 2; i++) {
                a[i][0] = packh2(z[i][2 * q][0],     z[i][2 * q][1]);
                a[i][1] = packh2(z[i][2 * q][2],     z[i][2 * q][3]);
                a[i][2] = packh2(z[i][2 * q + 1][0], z[i][2 * q + 1][1]);
                a[i][3] = packh2(z[i][2 * q + 1][2], z[i][2 * q + 1][3]);
            }
            #pragma unroll
            for (int j = 0; j < 8; j++) {
                uint2 b = sW1z[(j * 4 + q) * 32 + lane];
                mma16816(d[0][j], a[0], b);
                mma16816(d[1][j], a[1], b);
            }
        }

        // ---- h = relu(d), packed directly as A-fragments ----
        uint32_t ha[2][4][4];
        #pragma unroll
        for (int i = 0; i < 2; i++)
            #pragma unroll
            for (int q = 0; q < 4; q++) {
                ha[i][q][0] = packh2(fmaxf(d[i][2 * q][0], 0.f),     fmaxf(d[i][2 * q][1], 0.f));
                ha[i][q][1] = packh2(fmaxf(d[i][2 * q][2], 0.f),     fmaxf(d[i][2 * q][3], 0.f));
                ha[i][q][2] = packh2(fmaxf(d[i][2 * q + 1][0], 0.f), fmaxf(d[i][2 * q + 1][1], 0.f));
                ha[i][q][3] = packh2(fmaxf(d[i][2 * q + 1][2], 0.f), fmaxf(d[i][2 * q + 1][3], 0.f));
            }

        // ---- GEMM2: z = 0.9*z + 0.1*b2 + h @ (0.1*W2)^T  (z IS the accumulator)
        #pragma unroll
        for (int i = 0; i < 2; i++)
            #pragma unroll
            for (int j = 0; j < 8; j++) {
                z[i][j][0] = fmaf(0.9f, z[i][j][0], b2v[j][0]);
                z[i][j][1] = fmaf(0.9f, z[i][j][1], b2v[j][1]);
                z[i][j][2] = fmaf(0.9f, z[i][j][2], b2v[j][0]);
                z[i][j][3] = fmaf(0.9f, z[i][j][3], b2v[j][1]);
            }
        #pragma unroll
        for (int q = 0; q < 4; q++)
            #pragma unroll
            for (int j = 0; j < 8; j++) {
                uint2 b = sW2[(j * 4 + q) * 32 + lane];
                mma16816(z[0][j], ha[0][q], b);
                mma16816(z[1][j], ha[1][q], b);
            }
    }

    // ======================= logits = z @ class_emb^T =======================
    #pragma unroll 2
    for (int cls = 0; cls < NCLS; cls++) {
        float acc0 = 0.f, acc1 = 0.f, acc2 = 0.f, acc3 = 0.f;
        #pragma unroll
        for (int j = 0; j < 8; j++) {
            float2 ce = *(const float2*)(&sCE[cls * E + 8 * j + 2 * t4]);
            acc0 = fmaf(z[0][j][0], ce.x, fmaf(z[0][j][1], ce.y, acc0));
            acc1 = fmaf(z[0][j][2], ce.x, fmaf(z[0][j][3], ce.y, acc1));
            acc2 = fmaf(z[1][j][0], ce.x, fmaf(z[1][j][1], ce.y, acc2));
            acc3 = fmaf(z[1][j][2], ce.x, fmaf(z[1][j][3], ce.y, acc3));
        }
        acc0 += __shfl_xor_sync(0xffffffffu, acc0, 1);
        acc0 += __shfl_xor_sync(0xffffffffu, acc0, 2);
        acc1 += __shfl_xor_sync(0xffffffffu, acc1, 1);
        acc1 += __shfl_xor_sync(0xffffffffu, acc1, 2);
        acc2 += __shfl_xor_sync(0xffffffffu, acc2, 1);
        acc2 += __shfl_xor_sync(0xffffffffu, acc2, 2);
        acc3 += __shfl_xor_sync(0xffffffffu, acc3, 1);
        acc3 += __shfl_xor_sync(0xffffffffu, acc3, 2);
        if (t4 == 0) {
            int r0 = rowbase + g;
            if (r0 < Bn)      out[(size_t)r0 * NCLS + cls] = acc0;
            if (r0 + 8 < Bn)  out[(size_t)(r0 + 8) * NCLS + cls] = acc1;
            if (r0 + 16 < Bn) out[(size_t)(r0 + 16) * NCLS + cls] = acc2;
            if (r0 + 24 < Bn) out[(size_t)(r0 + 24) * NCLS + cls] = acc3;
        }
    }
}

// ============================================================================
// Launch
// ============================================================================
extern "C" void kernel_launch(void* const* d_in, const int* in_sizes, int n_in,
                              void* d_out, int out_size) {
    const float* x         = (const float*)d_in[0];
    const float* z0        = (const float*)d_in[1];
    const float* W_feat    = (const float*)d_in[2];
    const float* b_feat    = (const float*)d_in[3];
    const float* W1        = (const float*)d_in[4];
    const float* b1        = (const float*)d_in[5];
    const float* W2        = (const float*)d_in[6];
    const float* b2        = (const float*)d_in[7];
    const float* class_emb = (const float*)d_in[8];
    const int*   T_steps   = (n_in > 9) ? (const int*)d_in[9] : nullptr;
    float* out = (float*)d_out;

    int Bn = in_sizes[1] / E;   // z0 is [B, 64]

    prep_kernel<<<(10240 + E + 255) / 256, 256>>>(W_feat, b_feat, W1, b1, W2);

    int grid = (Bn + 127) / 128;
    iter_kernel<<<grid, 128>>>(x, z0, b2, class_emb, T_steps, out, Bn);
}

// round 15
// speedup vs baseline: 1.0335x; 1.0335x over previous
#include <cuda_runtime.h>
#include <cuda_fp16.h>
#include <cstdint>

// ============================================================================
// Portable tensor-core path: mma.sync.m16n8k16 (f16 in, f32 accum).
// The harness compiles for plain sm_100 (no 'a' suffix) -> no tcgen05.
//
// FINAL: proven-best configuration (R10, 163.9us, rel_err 2.05e-4).
// Iter kernel sits at the legacy-HMMA issue floor:
//   11.53M MMAs x rt_SMSP 16 / 592 SMSPs @ ~1.9GHz = 163.7us.
// Measured-out alternatives: 2x occupancy (same), fp16-accumulate (same rate),
// 1-warp CTAs (worse), FMA-pipe hybrid (2.2x worse), merged prep (worse).
// ============================================================================

static constexpr int E = 64;
static constexpr int IN_DIM = 512;
static constexpr int NCLS = 10;

#define SWZ(o) ((o) ^ (((o) >> 3) & 0x70))

__device__ __forceinline__ uint32_t packh2(float a, float b) {
    __half2 h = __floats2half2_rn(a, b);
    return *reinterpret_cast<uint32_t*>(&h);
}

__device__ __forceinline__ void mma16816(float d[4], const uint32_t a[4], uint2 b) {
    asm volatile(
        "mma.sync.aligned.m16n8k16.row.col.f32.f16.f16.f32 "
        "{%0,%1,%2,%3}, {%4,%5,%6,%7}, {%8,%9}, {%0,%1,%2,%3};\n"
        : "+f"(d[0]), "+f"(d[1]), "+f"(d[2]), "+f"(d[3])
        : "r"(a[0]), "r"(a[1]), "r"(a[2]), "r"(a[3]), "r"(b.x), "r"(b.y));
}

// ============================================================================
// Device scratch (no dynamic allocation allowed)
// ============================================================================
__device__ __align__(16) float g_WcP[4 * E * IN_DIM];   // 4-way e-split partials
__device__ __align__(16) uint2 g_W1zF[8 * 4 * 32];      // B-frags of W1[:, 64:128]
__device__ __align__(16) uint2 g_W2F[8 * 4 * 32];       // B-frags of 0.1*W2
__device__ __align__(16) uint2 g_WcF[32 * 8 * 32];      // B-frags of Wc (K=512)
__device__ __align__(16) float g_bias1[E];              // b1 + W1[:, :64] @ b_feat
__device__ __align__(16) float g_w1t[E];                // W1[:, 128]

// ============================================================================
// Prep 1: 4-way e-split partials of Wc = W1[:, :64] @ W_feat  (131K threads,
// coalesced over k)
// ============================================================================
__global__ void prep1_kernel(const float* __restrict__ W_feat,
                             const float* __restrict__ W1) {
    int idx = blockIdx.x * 256 + threadIdx.x;           // 131072 threads
    if (idx >= 4 * E * IN_DIM) return;
    int p = idx >> 15;
    int r = idx & 32767;
    int j = r >> 9, k = r & 511;
    int e0 = p * 16;
    float acc = 0.f;
    #pragma unroll
    for (int e = 0; e < 16; e++)
        acc = fmaf(W1[j * 129 + e0 + e], W_feat[(e0 + e) * IN_DIM + k], acc);
    g_WcP[idx] = acc;
}

// ============================================================================
// Prep 2: build per-lane B fragments + folded biases.
// B frag for m16n8k16.col: lane L (g=L>>2, t=L&3), n-tile j, k-chunk q:
//   b0 = {W[8j+g][16q+2t],   W[8j+g][16q+2t+1]}
//   b1 = {W[8j+g][16q+2t+8], W[8j+g][16q+2t+9]}
// ============================================================================
__global__ void prep2_kernel(const float* __restrict__ b_feat,
                             const float* __restrict__ W1,
                             const float* __restrict__ b1,
                             const float* __restrict__ W2) {
    int idx = blockIdx.x * 256 + threadIdx.x;
    if (idx < 8192) {                                   // WcF from partial sums
        int L = idx & 31, j = (idx >> 5) & 7, q = idx >> 8;
        int n = 8 * j + (L >> 2), k0 = 16 * q + 2 * (L & 3);
        float w[4];
        #pragma unroll
        for (int s = 0; s < 4; s++) {
            int k = k0 + (s & 1) + (s >> 1) * 8;        // k0, k0+1, k0+8, k0+9
            float acc = 0.f;
            #pragma unroll
            for (int p = 0; p < 4; p++) acc += g_WcP[p * 32768 + n * IN_DIM + k];
            w[s] = acc;
        }
        g_WcF[idx] = make_uint2(packh2(w[0], w[1]), packh2(w[2], w[3]));
    } else if (idx < 9216) {                            // W1zF
        int f = idx - 8192;
        int L = f & 31, q = (f >> 5) & 3, j = f >> 7;
        int n = 8 * j + (L >> 2), k0 = 16 * q + 2 * (L & 3);
        const float* w = W1 + n * 129 + 64;
        g_W1zF[f] = make_uint2(packh2(w[k0], w[k0 + 1]),
                               packh2(w[k0 + 8], w[k0 + 9]));
    } else if (idx < 10240) {                           // W2F (pre-scaled by 0.1)
        int f = idx - 9216;
        int L = f & 31, q = (f >> 5) & 3, j = f >> 7;
        int n = 8 * j + (L >> 2), k0 = 16 * q + 2 * (L & 3);
        const float* w = W2 + n * E;
        g_W2F[f] = make_uint2(packh2(0.1f * w[k0], 0.1f * w[k0 + 1]),
                              packh2(0.1f * w[k0 + 8], 0.1f * w[k0 + 9]));
    } else if (idx < 10240 + E) {                       // bias1, w1t
        int n = idx - 10240;
        float acc = b1[n];
        for (int e = 0; e < E; e++) acc += W1[n * 129 + e] * b_feat[e];
        g_bias1[n] = acc;
        g_w1t[n] = W1[n * 129 + 128];
    }
}

// ============================================================================
// Main kernel: 128 threads = 4 warps, 32 rows/warp. Register-resident
// recurrence, no in-loop synchronization of any kind.
// ============================================================================
__global__ __launch_bounds__(128, 2)
void iter_kernel(const float* __restrict__ x,
                 const float* __restrict__ z0,
                 const float* __restrict__ b2,
                 const float* __restrict__ class_emb,
                 const int* __restrict__ Tptr,
                 float* __restrict__ out,
                 int Bn) {
    __shared__ __align__(16) uint2 sW1z[1024];          // 8 KB
    __shared__ __align__(16) uint2 sW2[1024];           // 8 KB
    __shared__ float sBias1[E], sW1t[E], sB2s[E];
    __shared__ float sCE[NCLS * E];
    __shared__ __align__(128) char sX[128 * 128];       // 16 KB fp16, swizzled

    const int tid  = threadIdx.x;
    const int lane = tid & 31;
    const int g    = lane >> 2;
    const int t4   = lane & 3;
    const int warp = tid >> 5;
    const int ctabase = blockIdx.x * 128;
    const int rowbase = ctabase + warp * 32;

    // ---- cooperative weight/constant loads ----
    for (int i = tid; i < 1024; i += 128) { sW1z[i] = g_W1zF[i]; sW2[i] = g_W2F[i]; }
    if (tid < E) {
        sBias1[tid] = g_bias1[tid];
        sW1t[tid]   = g_w1t[tid];
        sB2s[tid]   = 0.1f * b2[tid];
    }
    for (int i = tid; i < NCLS * E; i += 128) sCE[i] = class_emb[i];

    // ======================= u = x @ Wc^T  (K = 512) =======================
    float u[2][8][4];
    #pragma unroll
    for (int i = 0; i < 2; i++)
        #pragma unroll
        for (int j = 0; j < 8; j++)
            #pragma unroll
            for (int c = 0; c < 4; c++) u[i][j][c] = 0.f;

    for (int ch = 0; ch < 8; ch++) {
        __syncthreads();   // protect sX reuse (also covers initial weight loads)
        // stage 128 rows x 64 cols fp32 -> fp16, swizzled
        for (int s = tid; s < 1024; s += 128) {
            int r = s >> 3, cq = s & 7;
            int rr = ctabase + r; if (rr >= Bn) rr = Bn - 1;
            const float4* p = (const float4*)(x + (size_t)rr * IN_DIM + ch * 64 + cq * 8);
            float4 v0 = p[0], v1 = p[1];
            uint4 pk;
            pk.x = packh2(v0.x, v0.y); pk.y = packh2(v0.z, v0.w);
            pk.z = packh2(v1.x, v1.y); pk.w = packh2(v1.z, v1.w);
            *(uint4*)(sX + SWZ(r * 128 + cq * 16)) = pk;
        }
        __syncthreads();
        #pragma unroll
        for (int q = 0; q < 4; q++) {
            uint32_t a[2][4];
            #pragma unroll
            for (int i = 0; i < 2; i++) {
                int rb0 = (warp * 32 + i * 16 + g) * 128;
                int rb1 = rb0 + 8 * 128;
                int cb  = q * 32 + t4 * 4;
                a[i][0] = *(const uint32_t*)(sX + SWZ(rb0 + cb));
                a[i][1] = *(const uint32_t*)(sX + SWZ(rb1 + cb));
                a[i][2] = *(const uint32_t*)(sX + SWZ(rb0 + cb + 16));
                a[i][3] = *(const uint32_t*)(sX + SWZ(rb1 + cb + 16));
            }
            #pragma unroll
            for (int j = 0; j < 8; j++) {
                uint2 b = g_WcF[((ch * 4 + q) * 8 + j) * 32 + lane];
                mma16816(u[0][j], a[0], b);
                mma16816(u[1][j], a[1], b);
            }
        }
    }
    __syncthreads();

    // ---- fold bias1 into u, compress to half2 (frees 32 regs) ----
    uint32_t uh[2][8][2];
    #pragma unroll
    for (int j = 0; j < 8; j++) {
        float b0 = sBias1[8 * j + 2 * t4], b1v = sBias1[8 * j + 2 * t4 + 1];
        #pragma unroll
        for (int i = 0; i < 2; i++) {
            uh[i][j][0] = packh2(u[i][j][0] + b0, u[i][j][1] + b1v);
            uh[i][j][1] = packh2(u[i][j][2] + b0, u[i][j][3] + b1v);
        }
    }

    float w1tv[8][2], b2v[8][2];
    #pragma unroll
    for (int j = 0; j < 8; j++) {
        w1tv[j][0] = sW1t[8 * j + 2 * t4];  w1tv[j][1] = sW1t[8 * j + 2 * t4 + 1];
        b2v[j][0]  = sB2s[8 * j + 2 * t4];  b2v[j][1]  = sB2s[8 * j + 2 * t4 + 1];
    }

    // ---- z0 -> registers (D-fragment layout, fp32 master) ----
    float z[2][8][4];
    #pragma unroll
    for (int i = 0; i < 2; i++) {
        int r0 = rowbase + i * 16 + g; if (r0 >= Bn) r0 = Bn - 1;
        int r1 = r0 + 8;               if (r1 >= Bn) r1 = Bn - 1;
        #pragma unroll
        for (int j = 0; j < 8; j++) {
            float2 v0 = *(const float2*)(z0 + (size_t)r0 * E + 8 * j + 2 * t4);
            float2 v1 = *(const float2*)(z0 + (size_t)r1 * E + 8 * j + 2 * t4);
            z[i][j][0] = v0.x; z[i][j][1] = v0.y;
            z[i][j][2] = v1.x; z[i][j][3] = v1.y;
        }
    }

    // ---- T ----
    int T = Tptr ? Tptr[0] : 40;
    if (T <= 0 || T > 1000000) {
        float tf = __int_as_float(T);
        T = (tf > 0.5f && tf < 1.0e6f) ? (int)tf : 40;
    }
    const float invT = 1.0f / (float)T;

    // ======================= 40-step recurrence (registers only) ============
    for (int step = 0; step < T; step++) {
        const float tv = (float)step * invT;

        // ---- GEMM1: d = u + t*w1t + z @ W1z^T ----
        float d[2][8][4];
        #pragma unroll
        for (int i = 0; i < 2; i++)
            #pragma unroll
            for (int j = 0; j < 8; j++) {
                float2 lo = __half22float2(*reinterpret_cast<__half2*>(&uh[i][j][0]));
                float2 hi = __half22float2(*reinterpret_cast<__half2*>(&uh[i][j][1]));
                d[i][j][0] = fmaf(tv, w1tv[j][0], lo.x);
                d[i][j][1] = fmaf(tv, w1tv[j][1], lo.y);
                d[i][j][2] = fmaf(tv, w1tv[j][0], hi.x);
                d[i][j][3] = fmaf(tv, w1tv[j][1], hi.y);
            }
        #pragma unroll
        for (int q = 0; q < 4; q++) {
            uint32_t a[2][4];
            #pragma unroll
            for (int i = 0; i < 2; i++) {
                a[i][0] = packh2(z[i][2 * q][0],     z[i][2 * q][1]);
                a[i][1] = packh2(z[i][2 * q][2],     z[i][2 * q][3]);
                a[i][2] = packh2(z[i][2 * q + 1][0], z[i][2 * q + 1][1]);
                a[i][3] = packh2(z[i][2 * q + 1][2], z[i][2 * q + 1][3]);
            }
            #pragma unroll
            for (int j = 0; j < 8; j++) {
                uint2 b = sW1z[(j * 4 + q) * 32 + lane];
                mma16816(d[0][j], a[0], b);
                mma16816(d[1][j], a[1], b);
            }
        }

        // ---- h = relu(d), packed directly as A-fragments ----
        uint32_t ha[2][4][4];
        #pragma unroll
        for (int i = 0; i < 2; i++)
            #pragma unroll
            for (int q = 0; q < 4; q++) {
                ha[i][q][0] = packh2(fmaxf(d[i][2 * q][0], 0.f),     fmaxf(d[i][2 * q][1], 0.f));
                ha[i][q][1] = packh2(fmaxf(d[i][2 * q][2], 0.f),     fmaxf(d[i][2 * q][3], 0.f));
                ha[i][q][2] = packh2(fmaxf(d[i][2 * q + 1][0], 0.f), fmaxf(d[i][2 * q + 1][1], 0.f));
                ha[i][q][3] = packh2(fmaxf(d[i][2 * q + 1][2], 0.f), fmaxf(d[i][2 * q + 1][3], 0.f));
            }

        // ---- GEMM2: z = 0.9*z + 0.1*b2 + h @ (0.1*W2)^T  (z IS the accumulator)
        #pragma unroll
        for (int i = 0; i < 2; i++)
            #pragma unroll
            for (int j = 0; j < 8; j++) {
                z[i][j][0] = fmaf(0.9f, z[i][j][0], b2v[j][0]);
                z[i][j][1] = fmaf(0.9f, z[i][j][1], b2v[j][1]);
                z[i][j][2] = fmaf(0.9f, z[i][j][2], b2v[j][0]);
                z[i][j][3] = fmaf(0.9f, z[i][j][3], b2v[j][1]);
            }
        #pragma unroll
        for (int q = 0; q < 4; q++)
            #pragma unroll
            for (int j = 0; j < 8; j++) {
                uint2 b = sW2[(j * 4 + q) * 32 + lane];
                mma16816(z[0][j], ha[0][q], b);
                mma16816(z[1][j], ha[1][q], b);
            }
    }

    // ======================= logits = z @ class_emb^T =======================
    #pragma unroll 2
    for (int cls = 0; cls < NCLS; cls++) {
        float acc0 = 0.f, acc1 = 0.f, acc2 = 0.f, acc3 = 0.f;
        #pragma unroll
        for (int j = 0; j < 8; j++) {
            float2 ce = *(const float2*)(&sCE[cls * E + 8 * j + 2 * t4]);
            acc0 = fmaf(z[0][j][0], ce.x, fmaf(z[0][j][1], ce.y, acc0));
            acc1 = fmaf(z[0][j][2], ce.x, fmaf(z[0][j][3], ce.y, acc1));
            acc2 = fmaf(z[1][j][0], ce.x, fmaf(z[1][j][1], ce.y, acc2));
            acc3 = fmaf(z[1][j][2], ce.x, fmaf(z[1][j][3], ce.y, acc3));
        }
        acc0 += __shfl_xor_sync(0xffffffffu, acc0, 1);
        acc0 += __shfl_xor_sync(0xffffffffu, acc0, 2);
        acc1 += __shfl_xor_sync(0xffffffffu, acc1, 1);
        acc1 += __shfl_xor_sync(0xffffffffu, acc1, 2);
        acc2 += __shfl_xor_sync(0xffffffffu, acc2, 1);
        acc2 += __shfl_xor_sync(0xffffffffu, acc2, 2);
        acc3 += __shfl_xor_sync(0xffffffffu, acc3, 1);
        acc3 += __shfl_xor_sync(0xffffffffu, acc3, 2);
        if (t4 == 0) {
            int r0 = rowbase + g;
            if (r0 < Bn)      out[(size_t)r0 * NCLS + cls] = acc0;
            if (r0 + 8 < Bn)  out[(size_t)(r0 + 8) * NCLS + cls] = acc1;
            if (r0 + 16 < Bn) out[(size_t)(r0 + 16) * NCLS + cls] = acc2;
            if (r0 + 24 < Bn) out[(size_t)(r0 + 24) * NCLS + cls] = acc3;
        }
    }
}

// ============================================================================
// Launch
// ============================================================================
extern "C" void kernel_launch(void* const* d_in, const int* in_sizes, int n_in,
                              void* d_out, int out_size) {
    const float* x         = (const float*)d_in[0];
    const float* z0        = (const float*)d_in[1];
    const float* W_feat    = (const float*)d_in[2];
    const float* b_feat    = (const float*)d_in[3];
    const float* W1        = (const float*)d_in[4];
    const float* b1        = (const float*)d_in[5];
    const float* W2        = (const float*)d_in[6];
    const float* b2        = (const float*)d_in[7];
    const float* class_emb = (const float*)d_in[8];
    const int*   T_steps   = (n_in > 9) ? (const int*)d_in[9] : nullptr;
    float* out = (float*)d_out;

    int Bn = in_sizes[1] / E;   // z0 is [B, 64]

    prep1_kernel<<<512, 256>>>(W_feat, W1);
    prep2_kernel<<<(10240 + E + 255) / 256, 256>>>(b_feat, W1, b1, W2);

    int grid = (Bn + 127) / 128;
    iter_kernel<<<grid, 128>>>(x, z0, b2, class_emb, T_steps, out, Bn);
}

// round 16
// speedup vs baseline: 1.0359x; 1.0023x over previous
#include <cuda_runtime.h>
#include <cuda_fp16.h>
#include <cstdint>

// ============================================================================
// FINAL KERNEL — IterativeClassifier on sm_100 (plain target, no tcgen05).
//
// Design: mma.sync.m16n8k16 (fp16 in, fp32 accum), fully register-resident
// 40-step recurrence, zero in-loop synchronization.
// Algebraic folds: Wc = W1[:,:64]@W_feat (features GEMM eliminated),
// bias1 = b1 + W1f@b_feat, W2 pre-scaled by 0.1, z is GEMM2's accumulator.
//
// At the legacy-HMMA issue floor: 11.53M MMAs x rt16 / 592 SMSP ~= 164us.
// Best measured: 163.9us, rel_err 2.05e-4.
// ============================================================================

static constexpr int E = 64;
static constexpr int IN_DIM = 512;
static constexpr int NCLS = 10;

#define SWZ(o) ((o) ^ (((o) >> 3) & 0x70))

__device__ __forceinline__ uint32_t packh2(float a, float b) {
    __half2 h = __floats2half2_rn(a, b);
    return *reinterpret_cast<uint32_t*>(&h);
}

__device__ __forceinline__ void mma16816(float d[4], const uint32_t a[4], uint2 b) {
    asm volatile(
        "mma.sync.aligned.m16n8k16.row.col.f32.f16.f16.f32 "
        "{%0,%1,%2,%3}, {%4,%5,%6,%7}, {%8,%9}, {%0,%1,%2,%3};\n"
        : "+f"(d[0]), "+f"(d[1]), "+f"(d[2]), "+f"(d[3])
        : "r"(a[0]), "r"(a[1]), "r"(a[2]), "r"(a[3]), "r"(b.x), "r"(b.y));
}

// ============================================================================
// Device scratch (no dynamic allocation allowed)
// ============================================================================
__device__ __align__(16) float g_WcP[4 * E * IN_DIM];   // 4-way e-split partials
__device__ __align__(16) uint2 g_W1zF[8 * 4 * 32];      // B-frags of W1[:, 64:128]
__device__ __align__(16) uint2 g_W2F[8 * 4 * 32];       // B-frags of 0.1*W2
__device__ __align__(16) uint2 g_WcF[32 * 8 * 32];      // B-frags of Wc (K=512)
__device__ __align__(16) float g_bias1[E];              // b1 + W1[:, :64] @ b_feat
__device__ __align__(16) float g_w1t[E];                // W1[:, 128]

// ============================================================================
// Prep 1: 4-way e-split partials of Wc = W1[:, :64] @ W_feat  (131K threads,
// coalesced over k)
// ============================================================================
__global__ void prep1_kernel(const float* __restrict__ W_feat,
                             const float* __restrict__ W1) {
    int idx = blockIdx.x * 256 + threadIdx.x;           // 131072 threads
    if (idx >= 4 * E * IN_DIM) return;
    int p = idx >> 15;
    int r = idx & 32767;
    int j = r >> 9, k = r & 511;
    int e0 = p * 16;
    float acc = 0.f;
    #pragma unroll
    for (int e = 0; e < 16; e++)
        acc = fmaf(W1[j * 129 + e0 + e], W_feat[(e0 + e) * IN_DIM + k], acc);
    g_WcP[idx] = acc;
}

// ============================================================================
// Prep 2: build per-lane B fragments + folded biases.
// B frag for m16n8k16.col: lane L (g=L>>2, t=L&3), n-tile j, k-chunk q:
//   b0 = {W[8j+g][16q+2t],   W[8j+g][16q+2t+1]}
//   b1 = {W[8j+g][16q+2t+8], W[8j+g][16q+2t+9]}
// ============================================================================
__global__ void prep2_kernel(const float* __restrict__ b_feat,
                             const float* __restrict__ W1,
                             const float* __restrict__ b1,
                             const float* __restrict__ W2) {
    int idx = blockIdx.x * 256 + threadIdx.x;
    if (idx < 8192) {                                   // WcF from partial sums
        int L = idx & 31, j = (idx >> 5) & 7, q = idx >> 8;
        int n = 8 * j + (L >> 2), k0 = 16 * q + 2 * (L & 3);
        float w[4];
        #pragma unroll
        for (int s = 0; s < 4; s++) {
            int k = k0 + (s & 1) + (s >> 1) * 8;        // k0, k0+1, k0+8, k0+9
            float acc = 0.f;
            #pragma unroll
            for (int p = 0; p < 4; p++) acc += g_WcP[p * 32768 + n * IN_DIM + k];
            w[s] = acc;
        }
        g_WcF[idx] = make_uint2(packh2(w[0], w[1]), packh2(w[2], w[3]));
    } else if (idx < 9216) {                            // W1zF
        int f = idx - 8192;
        int L = f & 31, q = (f >> 5) & 3, j = f >> 7;
        int n = 8 * j + (L >> 2), k0 = 16 * q + 2 * (L & 3);
        const float* w = W1 + n * 129 + 64;
        g_W1zF[f] = make_uint2(packh2(w[k0], w[k0 + 1]),
                               packh2(w[k0 + 8], w[k0 + 9]));
    } else if (idx < 10240) {                           // W2F (pre-scaled by 0.1)
        int f = idx - 9216;
        int L = f & 31, q = (f >> 5) & 3, j = f >> 7;
        int n = 8 * j + (L >> 2), k0 = 16 * q + 2 * (L & 3);
        const float* w = W2 + n * E;
        g_W2F[f] = make_uint2(packh2(0.1f * w[k0], 0.1f * w[k0 + 1]),
                              packh2(0.1f * w[k0 + 8], 0.1f * w[k0 + 9]));
    } else if (idx < 10240 + E) {                       // bias1, w1t
        int n = idx - 10240;
        float acc = b1[n];
        for (int e = 0; e < E; e++) acc += W1[n * 129 + e] * b_feat[e];
        g_bias1[n] = acc;
        g_w1t[n] = W1[n * 129 + 128];
    }
}

// ============================================================================
// Main kernel: 128 threads = 4 warps, 32 rows/warp. Register-resident
// recurrence, no in-loop synchronization of any kind.
// ============================================================================
__global__ __launch_bounds__(128, 2)
void iter_kernel(const float* __restrict__ x,
                 const float* __restrict__ z0,
                 const float* __restrict__ b2,
                 const float* __restrict__ class_emb,
                 const int* __restrict__ Tptr,
                 float* __restrict__ out,
                 int Bn) {
    __shared__ __align__(16) uint2 sW1z[1024];          // 8 KB
    __shared__ __align__(16) uint2 sW2[1024];           // 8 KB
    __shared__ float sBias1[E], sW1t[E], sB2s[E];
    __shared__ float sCE[NCLS * E];
    __shared__ __align__(128) char sX[128 * 128];       // 16 KB fp16, swizzled

    const int tid  = threadIdx.x;
    const int lane = tid & 31;
    const int g    = lane >> 2;
    const int t4   = lane & 3;
    const int warp = tid >> 5;
    const int ctabase = blockIdx.x * 128;
    const int rowbase = ctabase + warp * 32;

    // ---- cooperative weight/constant loads ----
    for (int i = tid; i < 1024; i += 128) { sW1z[i] = g_W1zF[i]; sW2[i] = g_W2F[i]; }
    if (tid < E) {
        sBias1[tid] = g_bias1[tid];
        sW1t[tid]   = g_w1t[tid];
        sB2s[tid]   = 0.1f * b2[tid];
    }
    for (int i = tid; i < NCLS * E; i += 128) sCE[i] = class_emb[i];

    // ======================= u = x @ Wc^T  (K = 512) =======================
    float u[2][8][4];
    #pragma unroll
    for (int i = 0; i < 2; i++)
        #pragma unroll
        for (int j = 0; j < 8; j++)
            #pragma unroll
            for (int c = 0; c < 4; c++) u[i][j][c] = 0.f;

    for (int ch = 0; ch < 8; ch++) {
        __syncthreads();   // protect sX reuse (also covers initial weight loads)
        // stage 128 rows x 64 cols fp32 -> fp16, swizzled
        for (int s = tid; s < 1024; s += 128) {
            int r = s >> 3, cq = s & 7;
            int rr = ctabase + r; if (rr >= Bn) rr = Bn - 1;
            const float4* p = (const float4*)(x + (size_t)rr * IN_DIM + ch * 64 + cq * 8);
            float4 v0 = p[0], v1 = p[1];
            uint4 pk;
            pk.x = packh2(v0.x, v0.y); pk.y = packh2(v0.z, v0.w);
            pk.z = packh2(v1.x, v1.y); pk.w = packh2(v1.z, v1.w);
            *(uint4*)(sX + SWZ(r * 128 + cq * 16)) = pk;
        }
        __syncthreads();
        #pragma unroll
        for (int q = 0; q < 4; q++) {
            uint32_t a[2][4];
            #pragma unroll
            for (int i = 0; i < 2; i++) {
                int rb0 = (warp * 32 + i * 16 + g) * 128;
                int rb1 = rb0 + 8 * 128;
                int cb  = q * 32 + t4 * 4;
                a[i][0] = *(const uint32_t*)(sX + SWZ(rb0 + cb));
                a[i][1] = *(const uint32_t*)(sX + SWZ(rb1 + cb));
                a[i][2] = *(const uint32_t*)(sX + SWZ(rb0 + cb + 16));
                a[i][3] = *(const uint32_t*)(sX + SWZ(rb1 + cb + 16));
            }
            #pragma unroll
            for (int j = 0; j < 8; j++) {
                uint2 b = g_WcF[((ch * 4 + q) * 8 + j) * 32 + lane];
                mma16816(u[0][j], a[0], b);
                mma16816(u[1][j], a[1], b);
            }
        }
    }
    __syncthreads();

    // ---- fold bias1 into u, compress to half2 (frees 32 regs) ----
    uint32_t uh[2][8][2];
    #pragma unroll
    for (int j = 0; j < 8; j++) {
        float b0 = sBias1[8 * j + 2 * t4], b1v = sBias1[8 * j + 2 * t4 + 1];
        #pragma unroll
        for (int i = 0; i < 2; i++) {
            uh[i][j][0] = packh2(u[i][j][0] + b0, u[i][j][1] + b1v);
            uh[i][j][1] = packh2(u[i][j][2] + b0, u[i][j][3] + b1v);
        }
    }

    float w1tv[8][2], b2v[8][2];
    #pragma unroll
    for (int j = 0; j < 8; j++) {
        w1tv[j][0] = sW1t[8 * j + 2 * t4];  w1tv[j][1] = sW1t[8 * j + 2 * t4 + 1];
        b2v[j][0]  = sB2s[8 * j + 2 * t4];  b2v[j][1]  = sB2s[8 * j + 2 * t4 + 1];
    }

    // ---- z0 -> registers (D-fragment layout, fp32 master) ----
    float z[2][8][4];
    #pragma unroll
    for (int i = 0; i < 2; i++) {
        int r0 = rowbase + i * 16 + g; if (r0 >= Bn) r0 = Bn - 1;
        int r1 = r0 + 8;               if (r1 >= Bn) r1 = Bn - 1;
        #pragma unroll
        for (int j = 0; j < 8; j++) {
            float2 v0 = *(const float2*)(z0 + (size_t)r0 * E + 8 * j + 2 * t4);
            float2 v1 = *(const float2*)(z0 + (size_t)r1 * E + 8 * j + 2 * t4);
            z[i][j][0] = v0.x; z[i][j][1] = v0.y;
            z[i][j][2] = v1.x; z[i][j][3] = v1.y;
        }
    }

    // ---- T ----
    int T = Tptr ? Tptr[0] : 40;
    if (T <= 0 || T > 1000000) {
        float tf = __int_as_float(T);
        T = (tf > 0.5f && tf < 1.0e6f) ? (int)tf : 40;
    }
    const float invT = 1.0f / (float)T;

    // ======================= 40-step recurrence (registers only) ============
    for (int step = 0; step < T; step++) {
        const float tv = (float)step * invT;

        // ---- GEMM1: d = u + t*w1t + z @ W1z^T ----
        float d[2][8][4];
        #pragma unroll
        for (int i = 0; i < 2; i++)
            #pragma unroll
            for (int j = 0; j < 8; j++) {
                float2 lo = __half22float2(*reinterpret_cast<__half2*>(&uh[i][j][0]));
                float2 hi = __half22float2(*reinterpret_cast<__half2*>(&uh[i][j][1]));
                d[i][j][0] = fmaf(tv, w1tv[j][0], lo.x);
                d[i][j][1] = fmaf(tv, w1tv[j][1], lo.y);
                d[i][j][2] = fmaf(tv, w1tv[j][0], hi.x);
                d[i][j][3] = fmaf(tv, w1tv[j][1], hi.y);
            }
        #pragma unroll
        for (int q = 0; q < 4; q++) {
            uint32_t a[2][4];
            #pragma unroll
            for (int i = 0; i < 2; i++) {
                a[i][0] = packh2(z[i][2 * q][0],     z[i][2 * q][1]);
                a[i][1] = packh2(z[i][2 * q][2],     z[i][2 * q][3]);
                a[i][2] = packh2(z[i][2 * q + 1][0], z[i][2 * q + 1][1]);
                a[i][3] = packh2(z[i][2 * q + 1][2], z[i][2 * q + 1][3]);
            }
            #pragma unroll
            for (int j = 0; j < 8; j++) {
                uint2 b = sW1z[(j * 4 + q) * 32 + lane];
                mma16816(d[0][j], a[0], b);
                mma16816(d[1][j], a[1], b);
            }
        }

        // ---- h = relu(d), packed directly as A-fragments ----
        uint32_t ha[2][4][4];
        #pragma unroll
        for (int i = 0; i < 2; i++)
            #pragma unroll
            for (int q = 0; q < 4; q++) {
                ha[i][q][0] = packh2(fmaxf(d[i][2 * q][0], 0.f),     fmaxf(d[i][2 * q][1], 0.f));
                ha[i][q][1] = packh2(fmaxf(d[i][2 * q][2], 0.f),     fmaxf(d[i][2 * q][3], 0.f));
                ha[i][q][2] = packh2(fmaxf(d[i][2 * q + 1][0], 0.f), fmaxf(d[i][2 * q + 1][1], 0.f));
                ha[i][q][3] = packh2(fmaxf(d[i][2 * q + 1][2], 0.f), fmaxf(d[i][2 * q + 1][3], 0.f));
            }

        // ---- GEMM2: z = 0.9*z + 0.1*b2 + h @ (0.1*W2)^T  (z IS the accumulator)
        #pragma unroll
        for (int i = 0; i < 2; i++)
            #pragma unroll
            for (int j = 0; j < 8; j++) {
                z[i][j][0] = fmaf(0.9f, z[i][j][0], b2v[j][0]);
                z[i][j][1] = fmaf(0.9f, z[i][j][1], b2v[j][1]);
                z[i][j][2] = fmaf(0.9f, z[i][j][2], b2v[j][0]);
                z[i][j][3] = fmaf(0.9f, z[i][j][3], b2v[j][1]);
            }
        #pragma unroll
        for (int q = 0; q < 4; q++)
            #pragma unroll
            for (int j = 0; j < 8; j++) {
                uint2 b = sW2[(j * 4 + q) * 32 + lane];
                mma16816(z[0][j], ha[0][q], b);
                mma16816(z[1][j], ha[1][q], b);
            }
    }

    // ======================= logits = z @ class_emb^T =======================
    #pragma unroll 2
    for (int cls = 0; cls < NCLS; cls++) {
        float acc0 = 0.f, acc1 = 0.f, acc2 = 0.f, acc3 = 0.f;
        #pragma unroll
        for (int j = 0; j < 8; j++) {
            float2 ce = *(const float2*)(&sCE[cls * E + 8 * j + 2 * t4]);
            acc0 = fmaf(z[0][j][0], ce.x, fmaf(z[0][j][1], ce.y, acc0));
            acc1 = fmaf(z[0][j][2], ce.x, fmaf(z[0][j][3], ce.y, acc1));
            acc2 = fmaf(z[1][j][0], ce.x, fmaf(z[1][j][1], ce.y, acc2));
            acc3 = fmaf(z[1][j][2], ce.x, fmaf(z[1][j][3], ce.y, acc3));
        }
        acc0 += __shfl_xor_sync(0xffffffffu, acc0, 1);
        acc0 += __shfl_xor_sync(0xffffffffu, acc0, 2);
        acc1 += __shfl_xor_sync(0xffffffffu, acc1, 1);
        acc1 += __shfl_xor_sync(0xffffffffu, acc1, 2);
        acc2 += __shfl_xor_sync(0xffffffffu, acc2, 1);
        acc2 += __shfl_xor_sync(0xffffffffu, acc2, 2);
        acc3 += __shfl_xor_sync(0xffffffffu, acc3, 1);
        acc3 += __shfl_xor_sync(0xffffffffu, acc3, 2);
        if (t4 == 0) {
            int r0 = rowbase + g;
            if (r0 < Bn)      out[(size_t)r0 * NCLS + cls] = acc0;
            if (r0 + 8 < Bn)  out[(size_t)(r0 + 8) * NCLS + cls] = acc1;
            if (r0 + 16 < Bn) out[(size_t)(r0 + 16) * NCLS + cls] = acc2;
            if (r0 + 24 < Bn) out[(size_t)(r0 + 24) * NCLS + cls] = acc3;
        }
    }
}

// ============================================================================
// Launch
// ============================================================================
extern "C" void kernel_launch(void* const* d_in, const int* in_sizes, int n_in,
                              void* d_out, int out_size) {
    const float* x         = (const float*)d_in[0];
    const float* z0        = (const float*)d_in[1];
    const float* W_feat    = (const float*)d_in[2];
    const float* b_feat    = (const float*)d_in[3];
    const float* W1        = (const float*)d_in[4];
    const float* b1        = (const float*)d_in[5];
    const float* W2        = (const float*)d_in[6];
    const float* b2        = (const float*)d_in[7];
    const float* class_emb = (const float*)d_in[8];
    const int*   T_steps   = (n_in > 9) ? (const int*)d_in[9] : nullptr;
    float* out = (float*)d_out;

    int Bn = in_sizes[1] / E;   // z0 is [B, 64]

    prep1_kernel<<<512, 256>>>(W_feat, W1);
    prep2_kernel<<<(10240 + E + 255) / 256, 256>>>(b_feat, W1, b1, W2);

    int grid = (Bn + 127) / 128;
    iter_kernel<<<grid, 128>>>(x, z0, b2, class_emb, T_steps, out, Bn);
}

// round 17
// speedup vs baseline: 1.0361x; 1.0002x over previous
#include <cuda_runtime.h>
#include <cuda_fp16.h>
#include <cstdint>

// ============================================================================
// FINAL KERNEL — IterativeClassifier on sm_100 (plain target, no tcgen05).
//
// Design: mma.sync.m16n8k16 (fp16 in, fp32 accum), fully register-resident
// 40-step recurrence, zero in-loop synchronization.
// Algebraic folds: Wc = W1[:,:64]@W_feat (features GEMM eliminated),
// bias1 = b1 + W1f@b_feat, W2 pre-scaled by 0.1, z is GEMM2's accumulator.
//
// At the legacy-HMMA issue floor: 11.53M MMAs x rt16 / 592 SMSP ~= 164us.
// Best measured: 163.9us, rel_err 2.05e-4 (3x reproduced).
// ============================================================================

static constexpr int E = 64;
static constexpr int IN_DIM = 512;
static constexpr int NCLS = 10;

#define SWZ(o) ((o) ^ (((o) >> 3) & 0x70))

__device__ __forceinline__ uint32_t packh2(float a, float b) {
    __half2 h = __floats2half2_rn(a, b);
    return *reinterpret_cast<uint32_t*>(&h);
}

__device__ __forceinline__ void mma16816(float d[4], const uint32_t a[4], uint2 b) {
    asm volatile(
        "mma.sync.aligned.m16n8k16.row.col.f32.f16.f16.f32 "
        "{%0,%1,%2,%3}, {%4,%5,%6,%7}, {%8,%9}, {%0,%1,%2,%3};\n"
        : "+f"(d[0]), "+f"(d[1]), "+f"(d[2]), "+f"(d[3])
        : "r"(a[0]), "r"(a[1]), "r"(a[2]), "r"(a[3]), "r"(b.x), "r"(b.y));
}

// ============================================================================
// Device scratch (no dynamic allocation allowed)
// ============================================================================
__device__ __align__(16) float g_WcP[4 * E * IN_DIM];   // 4-way e-split partials
__device__ __align__(16) uint2 g_W1zF[8 * 4 * 32];      // B-frags of W1[:, 64:128]
__device__ __align__(16) uint2 g_W2F[8 * 4 * 32];       // B-frags of 0.1*W2
__device__ __align__(16) uint2 g_WcF[32 * 8 * 32];      // B-frags of Wc (K=512)
__device__ __align__(16) float g_bias1[E];              // b1 + W1[:, :64] @ b_feat
__device__ __align__(16) float g_w1t[E];                // W1[:, 128]

// ============================================================================
// Prep 1: 4-way e-split partials of Wc = W1[:, :64] @ W_feat  (131K threads,
// coalesced over k)
// ============================================================================
__global__ void prep1_kernel(const float* __restrict__ W_feat,
                             const float* __restrict__ W1) {
    int idx = blockIdx.x * 256 + threadIdx.x;           // 131072 threads
    if (idx >= 4 * E * IN_DIM) return;
    int p = idx >> 15;
    int r = idx & 32767;
    int j = r >> 9, k = r & 511;
    int e0 = p * 16;
    float acc = 0.f;
    #pragma unroll
    for (int e = 0; e < 16; e++)
        acc = fmaf(W1[j * 129 + e0 + e], W_feat[(e0 + e) * IN_DIM + k], acc);
    g_WcP[idx] = acc;
}

// ============================================================================
// Prep 2: build per-lane B fragments + folded biases.
// B frag for m16n8k16.col: lane L (g=L>>2, t=L&3), n-tile j, k-chunk q:
//   b0 = {W[8j+g][16q+2t],   W[8j+g][16q+2t+1]}
//   b1 = {W[8j+g][16q+2t+8], W[8j+g][16q+2t+9]}
// ============================================================================
__global__ void prep2_kernel(const float* __restrict__ b_feat,
                             const float* __restrict__ W1,
                             const float* __restrict__ b1,
                             const float* __restrict__ W2) {
    int idx = blockIdx.x * 256 + threadIdx.x;
    if (idx < 8192) {                                   // WcF from partial sums
        int L = idx & 31, j = (idx >> 5) & 7, q = idx >> 8;
        int n = 8 * j + (L >> 2), k0 = 16 * q + 2 * (L & 3);
        float w[4];
        #pragma unroll
        for (int s = 0; s < 4; s++) {
            int k = k0 + (s & 1) + (s >> 1) * 8;        // k0, k0+1, k0+8, k0+9
            float acc = 0.f;
            #pragma unroll
            for (int p = 0; p < 4; p++) acc += g_WcP[p * 32768 + n * IN_DIM + k];
            w[s] = acc;
        }
        g_WcF[idx] = make_uint2(packh2(w[0], w[1]), packh2(w[2], w[3]));
    } else if (idx < 9216) {                            // W1zF
        int f = idx - 8192;
        int L = f & 31, q = (f >> 5) & 3, j = f >> 7;
        int n = 8 * j + (L >> 2), k0 = 16 * q + 2 * (L & 3);
        const float* w = W1 + n * 129 + 64;
        g_W1zF[f] = make_uint2(packh2(w[k0], w[k0 + 1]),
                               packh2(w[k0 + 8], w[k0 + 9]));
    } else if (idx < 10240) {                           // W2F (pre-scaled by 0.1)
        int f = idx - 9216;
        int L = f & 31, q = (f >> 5) & 3, j = f >> 7;
        int n = 8 * j + (L >> 2), k0 = 16 * q + 2 * (L & 3);
        const float* w = W2 + n * E;
        g_W2F[f] = make_uint2(packh2(0.1f * w[k0], 0.1f * w[k0 + 1]),
                              packh2(0.1f * w[k0 + 8], 0.1f * w[k0 + 9]));
    } else if (idx < 10240 + E) {                       // bias1, w1t
        int n = idx - 10240;
        float acc = b1[n];
        for (int e = 0; e < E; e++) acc += W1[n * 129 + e] * b_feat[e];
        g_bias1[n] = acc;
        g_w1t[n] = W1[n * 129 + 128];
    }
}

// ============================================================================
// Main kernel: 128 threads = 4 warps, 32 rows/warp. Register-resident
// recurrence, no in-loop synchronization of any kind.
// ============================================================================
__global__ __launch_bounds__(128, 2)
void iter_kernel(const float* __restrict__ x,
                 const float* __restrict__ z0,
                 const float* __restrict__ b2,
                 const float* __restrict__ class_emb,
                 const int* __restrict__ Tptr,
                 float* __restrict__ out,
                 int Bn) {
    __shared__ __align__(16) uint2 sW1z[1024];          // 8 KB
    __shared__ __align__(16) uint2 sW2[1024];           // 8 KB
    __shared__ float sBias1[E], sW1t[E], sB2s[E];
    __shared__ float sCE[NCLS * E];
    __shared__ __align__(128) char sX[128 * 128];       // 16 KB fp16, swizzled

    const int tid  = threadIdx.x;
    const int lane = tid & 31;
    const int g    = lane >> 2;
    const int t4   = lane & 3;
    const int warp = tid >> 5;
    const int ctabase = blockIdx.x * 128;
    const int rowbase = ctabase + warp * 32;

    // ---- cooperative weight/constant loads ----
    for (int i = tid; i < 1024; i += 128) { sW1z[i] = g_W1zF[i]; sW2[i] = g_W2F[i]; }
    if (tid < E) {
        sBias1[tid] = g_bias1[tid];
        sW1t[tid]   = g_w1t[tid];
        sB2s[tid]   = 0.1f * b2[tid];
    }
    for (int i = tid; i < NCLS * E; i += 128) sCE[i] = class_emb[i];

    // ======================= u = x @ Wc^T  (K = 512) =======================
    float u[2][8][4];
    #pragma unroll
    for (int i = 0; i < 2; i++)
        #pragma unroll
        for (int j = 0; j < 8; j++)
            #pragma unroll
            for (int c = 0; c < 4; c++) u[i][j][c] = 0.f;

    for (int ch = 0; ch < 8; ch++) {
        __syncthreads();   // protect sX reuse (also covers initial weight loads)
        // stage 128 rows x 64 cols fp32 -> fp16, swizzled
        for (int s = tid; s < 1024; s += 128) {
            int r = s >> 3, cq = s & 7;
            int rr = ctabase + r; if (rr >= Bn) rr = Bn - 1;
            const float4* p = (const float4*)(x + (size_t)rr * IN_DIM + ch * 64 + cq * 8);
            float4 v0 = p[0], v1 = p[1];
            uint4 pk;
            pk.x = packh2(v0.x, v0.y); pk.y = packh2(v0.z, v0.w);
            pk.z = packh2(v1.x, v1.y); pk.w = packh2(v1.z, v1.w);
            *(uint4*)(sX + SWZ(r * 128 + cq * 16)) = pk;
        }
        __syncthreads();
        #pragma unroll
        for (int q = 0; q < 4; q++) {
            uint32_t a[2][4];
            #pragma unroll
            for (int i = 0; i < 2; i++) {
                int rb0 = (warp * 32 + i * 16 + g) * 128;
                int rb1 = rb0 + 8 * 128;
                int cb  = q * 32 + t4 * 4;
                a[i][0] = *(const uint32_t*)(sX + SWZ(rb0 + cb));
                a[i][1] = *(const uint32_t*)(sX + SWZ(rb1 + cb));
                a[i][2] = *(const uint32_t*)(sX + SWZ(rb0 + cb + 16));
                a[i][3] = *(const uint32_t*)(sX + SWZ(rb1 + cb + 16));
            }
            #pragma unroll
            for (int j = 0; j < 8; j++) {
                uint2 b = g_WcF[((ch * 4 + q) * 8 + j) * 32 + lane];
                mma16816(u[0][j], a[0], b);
                mma16816(u[1][j], a[1], b);
            }
        }
    }
    __syncthreads();

    // ---- fold bias1 into u, compress to half2 (frees 32 regs) ----
    uint32_t uh[2][8][2];
    #pragma unroll
    for (int j = 0; j < 8; j++) {
        float b0 = sBias1[8 * j + 2 * t4], b1v = sBias1[8 * j + 2 * t4 + 1];
        #pragma unroll
        for (int i = 0; i < 2; i++) {
            uh[i][j][0] = packh2(u[i][j][0] + b0, u[i][j][1] + b1v);
            uh[i][j][1] = packh2(u[i][j][2] + b0, u[i][j][3] + b1v);
        }
    }

    float w1tv[8][2], b2v[8][2];
    #pragma unroll
    for (int j = 0; j < 8; j++) {
        w1tv[j][0] = sW1t[8 * j + 2 * t4];  w1tv[j][1] = sW1t[8 * j + 2 * t4 + 1];
        b2v[j][0]  = sB2s[8 * j + 2 * t4];  b2v[j][1]  = sB2s[8 * j + 2 * t4 + 1];
    }

    // ---- z0 -> registers (D-fragment layout, fp32 master) ----
    float z[2][8][4];
    #pragma unroll
    for (int i = 0; i < 2; i++) {
        int r0 = rowbase + i * 16 + g; if (r0 >= Bn) r0 = Bn - 1;
        int r1 = r0 + 8;               if (r1 >= Bn) r1 = Bn - 1;
        #pragma unroll
        for (int j = 0; j < 8; j++) {
            float2 v0 = *(const float2*)(z0 + (size_t)r0 * E + 8 * j + 2 * t4);
            float2 v1 = *(const float2*)(z0 + (size_t)r1 * E + 8 * j + 2 * t4);
            z[i][j][0] = v0.x; z[i][j][1] = v0.y;
            z[i][j][2] = v1.x; z[i][j][3] = v1.y;
        }
    }

    // ---- T ----
    int T = Tptr ? Tptr[0] : 40;
    if (T <= 0 || T > 1000000) {
        float tf = __int_as_float(T);
        T = (tf > 0.5f && tf < 1.0e6f) ? (int)tf : 40;
    }
    const float invT = 1.0f / (float)T;

    // ======================= 40-step recurrence (registers only) ============
    for (int step = 0; step < T; step++) {
        const float tv = (float)step * invT;

        // ---- GEMM1: d = u + t*w1t + z @ W1z^T ----
        float d[2][8][4];
        #pragma unroll
        for (int i = 0; i < 2; i++)
            #pragma unroll
            for (int j = 0; j < 8; j++) {
                float2 lo = __half22float2(*reinterpret_cast<__half2*>(&uh[i][j][0]));
                float2 hi = __half22float2(*reinterpret_cast<__half2*>(&uh[i][j][1]));
                d[i][j][0] = fmaf(tv, w1tv[j][0], lo.x);
                d[i][j][1] = fmaf(tv, w1tv[j][1], lo.y);
                d[i][j][2] = fmaf(tv, w1tv[j][0], hi.x);
                d[i][j][3] = fmaf(tv, w1tv[j][1], hi.y);
            }
        #pragma unroll
        for (int q = 0; q < 4; q++) {
            uint32_t a[2][4];
            #pragma unroll
            for (int i = 0; i < 2; i++) {
                a[i][0] = packh2(z[i][2 * q][0],     z[i][2 * q][1]);
                a[i][1] = packh2(z[i][2 * q][2],     z[i][2 * q][3]);
                a[i][2] = packh2(z[i][2 * q + 1][0], z[i][2 * q + 1][1]);
                a[i][3] = packh2(z[i][2 * q + 1][2], z[i][2 * q + 1][3]);
            }
            #pragma unroll
            for (int j = 0; j < 8; j++) {
                uint2 b = sW1z[(j * 4 + q) * 32 + lane];
                mma16816(d[0][j], a[0], b);
                mma16816(d[1][j], a[1], b);
            }
        }

        // ---- h = relu(d), packed directly as A-fragments ----
        uint32_t ha[2][4][4];
        #pragma unroll
        for (int i = 0; i < 2; i++)
            #pragma unroll
            for (int q = 0; q < 4; q++) {
                ha[i][q][0] = packh2(fmaxf(d[i][2 * q][0], 0.f),     fmaxf(d[i][2 * q][1], 0.f));
                ha[i][q][1] = packh2(fmaxf(d[i][2 * q][2], 0.f),     fmaxf(d[i][2 * q][3], 0.f));
                ha[i][q][2] = packh2(fmaxf(d[i][2 * q + 1][0], 0.f), fmaxf(d[i][2 * q + 1][1], 0.f));
                ha[i][q][3] = packh2(fmaxf(d[i][2 * q + 1][2], 0.f), fmaxf(d[i][2 * q + 1][3], 0.f));
            }

        // ---- GEMM2: z = 0.9*z + 0.1*b2 + h @ (0.1*W2)^T  (z IS the accumulator)
        #pragma unroll
        for (int i = 0; i < 2; i++)
            #pragma unroll
            for (int j = 0; j < 8; j++) {
                z[i][j][0] = fmaf(0.9f, z[i][j][0], b2v[j][0]);
                z[i][j][1] = fmaf(0.9f, z[i][j][1], b2v[j][1]);
                z[i][j][2] = fmaf(0.9f, z[i][j][2], b2v[j][0]);
                z[i][j][3] = fmaf(0.9f, z[i][j][3], b2v[j][1]);
            }
        #pragma unroll
        for (int q = 0; q < 4; q++)
            #pragma unroll
            for (int j = 0; j < 8; j++) {
                uint2 b = sW2[(j * 4 + q) * 32 + lane];
                mma16816(z[0][j], ha[0][q], b);
                mma16816(z[1][j], ha[1][q], b);
            }
    }

    // ======================= logits = z @ class_emb^T =======================
    #pragma unroll 2
    for (int cls = 0; cls < NCLS; cls++) {
        float acc0 = 0.f, acc1 = 0.f, acc2 = 0.f, acc3 = 0.f;
        #pragma unroll
        for (int j = 0; j < 8; j++) {
            float2 ce = *(const float2*)(&sCE[cls * E + 8 * j + 2 * t4]);
            acc0 = fmaf(z[0][j][0], ce.x, fmaf(z[0][j][1], ce.y, acc0));
            acc1 = fmaf(z[0][j][2], ce.x, fmaf(z[0][j][3], ce.y, acc1));
            acc2 = fmaf(z[1][j][0], ce.x, fmaf(z[1][j][1], ce.y, acc2));
            acc3 = fmaf(z[1][j][2], ce.x, fmaf(z[1][j][3], ce.y, acc3));
        }
        acc0 += __shfl_xor_sync(0xffffffffu, acc0, 1);
        acc0 += __shfl_xor_sync(0xffffffffu, acc0, 2);
        acc1 += __shfl_xor_sync(0xffffffffu, acc1, 1);
        acc1 += __shfl_xor_sync(0xffffffffu, acc1, 2);
        acc2 += __shfl_xor_sync(0xffffffffu, acc2, 1);
        acc2 += __shfl_xor_sync(0xffffffffu, acc2, 2);
        acc3 += __shfl_xor_sync(0xffffffffu, acc3, 1);
        acc3 += __shfl_xor_sync(0xffffffffu, acc3, 2);
        if (t4 == 0) {
            int r0 = rowbase + g;
            if (r0 < Bn)      out[(size_t)r0 * NCLS + cls] = acc0;
            if (r0 + 8 < Bn)  out[(size_t)(r0 + 8) * NCLS + cls] = acc1;
            if (r0 + 16 < Bn) out[(size_t)(r0 + 16) * NCLS + cls] = acc2;
            if (r0 + 24 < Bn) out[(size_t)(r0 + 24) * NCLS + cls] = acc3;
        }
    }
}

// ============================================================================
// Launch
// ============================================================================
extern "C" void kernel_launch(void* const* d_in, const int* in_sizes, int n_in,
                              void* d_out, int out_size) {
    const float* x         = (const float*)d_in[0];
    const float* z0        = (const float*)d_in[1];
    const float* W_feat    = (const float*)d_in[2];
    const float* b_feat    = (const float*)d_in[3];
    const float* W1        = (const float*)d_in[4];
    const float* b1        = (const float*)d_in[5];
    const float* W2        = (const float*)d_in[6];
    const float* b2        = (const float*)d_in[7];
    const float* class_emb = (const float*)d_in[8];
    const int*   T_steps   = (n_in > 9) ? (const int*)d_in[9] : nullptr;
    float* out = (float*)d_out;

    int Bn = in_sizes[1] / E;   // z0 is [B, 64]

    prep1_kernel<<<512, 256>>>(W_feat, W1);
    prep2_kernel<<<(10240 + E + 255) / 256, 256>>>(b_feat, W1, b1, W2);

    int grid = (Bn + 127) / 128;
    iter_kernel<<<grid, 128>>>(x, z0, b2, class_emb, T_steps, out, Bn);
}